// round 15
// baseline (speedup 1.0000x reference)
#include <cuda_runtime.h>
#include <cuda_bf16.h>
#include <math.h>
#include <stdint.h>
#include <cstdint>

// ---------------------------------------------------------------------------
// Problem dims (fixed)
// ---------------------------------------------------------------------------
#define DIM_B 16
#define DIM_T 512
#define DIM_S 128
#define DIM_M 16
#define DIM_D 512
#define NROWS (DIM_B * DIM_T)        // 8192
#define ERR_ROWS (DIM_S * DIM_M)     // 2048

#define TAU_STEP 0.07f
#define TAU_ERR  0.07f
#define RHO_ERR  0.85f
#define K_MAX    5
#define LAM_SELF 1.0f
#define LAM_SUCC 0.8f
#define LAM_PRED 0.4f
#define LAM_TOPO 0.5f
#define LOG16    2.772588722239781f

// Output layout (floats), in reference tuple order
#define ALPHA_OFF 0
#define GAMMA_OFF (ALPHA_OFF + NROWS * DIM_S)
#define BETA_OFF  (GAMMA_OFF + NROWS * DIM_S * DIM_M)
#define STEP_OFF  (BETA_OFF  + NROWS * DIM_S * DIM_M)
#define ERRO_OFF  (STEP_OFF  + NROWS * DIM_D)
#define AUX_OFF   (ERRO_OFF  + NROWS * DIM_D)
#define CMASK_OFF (AUX_OFF   + NROWS * 8)
#define RAW_OFF   (CMASK_OFF + NROWS * DIM_S)

// ---------------------------------------------------------------------------
// Scratch (static device globals: allocation-free)
// ---------------------------------------------------------------------------
__device__ float g_qstep[NROWS * DIM_D];
__device__ float g_qerr [NROWS * DIM_D];
__device__ float g_stepproto [DIM_S * DIM_D];
__device__ float g_stepprotoT[DIM_D * DIM_S];
__device__ float g_errproto[ERR_ROWS * DIM_D];
__device__ float g_rinv_qstep[NROWS];
__device__ float g_rinv_qerr [NROWS];

// ---------------------------------------------------------------------------
// TF32 helpers
// ---------------------------------------------------------------------------
__device__ __forceinline__ void split_tf32(float x, uint32_t& hi, uint32_t& lo) {
    uint32_t h = __float_as_uint(x) & 0xFFFFE000u;
    hi = h;
    lo = __float_as_uint(x - __uint_as_float(h));
}

__device__ __forceinline__ void mma_m16n8k8(float* c, const uint32_t* a, const uint32_t* b) {
    asm volatile(
        "mma.sync.aligned.m16n8k8.row.col.f32.tf32.tf32.f32 "
        "{%0,%1,%2,%3}, {%4,%5,%6,%7}, {%8,%9}, {%0,%1,%2,%3};\n"
        : "+f"(c[0]), "+f"(c[1]), "+f"(c[2]), "+f"(c[3])
        : "r"(a[0]), "r"(a[1]), "r"(a[2]), "r"(a[3]), "r"(b[0]), "r"(b[1]));
}

// ---------------------------------------------------------------------------
// TF32 (3x split) GEMM NT (R9 champion inner loop) with optional per-row
// output scale: C[m,n] = scale * rowscale[m] * (sum_k A[m,k]*B[n,k] + bias[n])
// ---------------------------------------------------------------------------
template<int BM, int BN, int WM, int WN>
__global__ void __launch_bounds__((BM / WM) * (BN / WN) * 32)
mma_nt(const float* __restrict__ A, const float* __restrict__ B,
       const float* __restrict__ bias, const float* __restrict__ rowscale,
       float* __restrict__ C, int M, int N, int K, float scale)
{
    constexpr int WARPS_M = BM / WM;
    constexpr int WARPS_N = BN / WN;
    constexpr int NTHREADS = WARPS_M * WARPS_N * 32;
    constexpr int FM = WM / 16;
    constexpr int FN = WN / 8;
    constexpr int LDA = 20;
    constexpr int LA = BM * 4 / NTHREADS;
    constexpr int LB = BN * 4 / NTHREADS;

    __shared__ __align__(16) float sA[2][BM * LDA];
    __shared__ __align__(16) float sB[2][BN * LDA];

    const int tid = threadIdx.x;
    const int lane = tid & 31;
    const int warp = tid >> 5;
    const int gid = lane >> 2, tig = lane & 3;
    const int wm0 = (warp % WARPS_M) * WM;
    const int wn0 = (warp / WARPS_M) * WN;
    const int bm = blockIdx.y * BM;
    const int bn = blockIdx.x * BN;

    float acc[FM][FN][4];
#pragma unroll
    for (int i = 0; i < FM; i++)
#pragma unroll
        for (int j = 0; j < FN; j++)
#pragma unroll
            for (int q = 0; q < 4; q++) acc[i][j][q] = 0.f;

    float4 stageA[LA], stageB[LB];

    auto gload = [&](int kt) {
        int k0 = kt * 16;
#pragma unroll
        for (int i = 0; i < LA; i++) {
            int c = tid + i * NTHREADS;
            int row = c >> 2, kc = (c & 3) << 2;
            stageA[i] = *(const float4*)(A + (size_t)(bm + row) * K + k0 + kc);
        }
#pragma unroll
        for (int i = 0; i < LB; i++) {
            int c = tid + i * NTHREADS;
            int row = c >> 2, kc = (c & 3) << 2;
            stageB[i] = *(const float4*)(B + (size_t)(bn + row) * K + k0 + kc);
        }
    };

    auto sstore = [&](int buf) {
#pragma unroll
        for (int i = 0; i < LA; i++) {
            int c = tid + i * NTHREADS;
            int row = c >> 2, kc = (c & 3) << 2;
            *(float4*)(&sA[buf][row * LDA + kc]) = stageA[i];
        }
#pragma unroll
        for (int i = 0; i < LB; i++) {
            int c = tid + i * NTHREADS;
            int row = c >> 2, kc = (c & 3) << 2;
            *(float4*)(&sB[buf][row * LDA + kc]) = stageB[i];
        }
    };

    const int KT = K >> 4;
    gload(0);
    sstore(0);
    __syncthreads();

    int buf = 0;
    for (int kt = 0; kt < KT; kt++) {
        if (kt + 1 < KT) gload(kt + 1);

#pragma unroll
        for (int ks = 0; ks < 2; ks++) {
            uint32_t ahi[FM][4], alo[FM][4];
#pragma unroll
            for (int fm = 0; fm < FM; fm++) {
                int r = wm0 + fm * 16 + gid;
                float x0 = sA[buf][r * LDA + ks * 8 + tig];
                float x1 = sA[buf][(r + 8) * LDA + ks * 8 + tig];
                float x2 = sA[buf][r * LDA + ks * 8 + tig + 4];
                float x3 = sA[buf][(r + 8) * LDA + ks * 8 + tig + 4];
                split_tf32(x0, ahi[fm][0], alo[fm][0]);
                split_tf32(x1, ahi[fm][1], alo[fm][1]);
                split_tf32(x2, ahi[fm][2], alo[fm][2]);
                split_tf32(x3, ahi[fm][3], alo[fm][3]);
            }
#pragma unroll
            for (int fn = 0; fn < FN; fn++) {
                int n = wn0 + fn * 8 + gid;
                float y0 = sB[buf][n * LDA + ks * 8 + tig];
                float y1 = sB[buf][n * LDA + ks * 8 + tig + 4];
                uint32_t bhi[2], blo[2];
                split_tf32(y0, bhi[0], blo[0]);
                split_tf32(y1, bhi[1], blo[1]);
#pragma unroll
                for (int fm = 0; fm < FM; fm++) {
                    mma_m16n8k8(acc[fm][fn], alo[fm], bhi);
                    mma_m16n8k8(acc[fm][fn], ahi[fm], blo);
                    mma_m16n8k8(acc[fm][fn], ahi[fm], bhi);
                }
            }
        }

        if (kt + 1 < KT) sstore(buf ^ 1);
        __syncthreads();
        buf ^= 1;
    }

#pragma unroll
    for (int fm = 0; fm < FM; fm++) {
        int r0 = bm + wm0 + fm * 16 + gid;
        float rs0 = scale, rs1 = scale;
        if (rowscale) { rs0 *= rowscale[r0]; rs1 *= rowscale[r0 + 8]; }
#pragma unroll
        for (int fn = 0; fn < FN; fn++) {
            int c0 = bn + wn0 + fn * 8 + 2 * tig;
            float bx = 0.f, by = 0.f;
            if (bias) { bx = bias[c0]; by = bias[c0 + 1]; }
            float2 v0, v1;
            v0.x = (acc[fm][fn][0] + bx) * rs0;
            v0.y = (acc[fm][fn][1] + by) * rs0;
            v1.x = (acc[fm][fn][2] + bx) * rs1;
            v1.y = (acc[fm][fn][3] + by) * rs1;
            *(float2*)(C + (size_t)r0 * N + c0) = v0;
            *(float2*)(C + (size_t)(r0 + 8) * N + c0) = v1;
        }
    }
}

// ---------------------------------------------------------------------------
// Row-wise L2 normalize (in place), width 512. One warp per row.
// ---------------------------------------------------------------------------
__global__ void normalize_rows(float* __restrict__ X, int R)
{
    int row = blockIdx.x * 4 + (threadIdx.x >> 5);
    int lane = threadIdx.x & 31;
    if (row >= R) return;
    float4* p = (float4*)(X + (size_t)row * DIM_D);
    float4 v[4];
    float ss = 0.f;
#pragma unroll
    for (int i = 0; i < 4; i++) {
        v[i] = p[lane + 32 * i];
        ss += v[i].x * v[i].x + v[i].y * v[i].y + v[i].z * v[i].z + v[i].w * v[i].w;
    }
#pragma unroll
    for (int o = 16; o > 0; o >>= 1) ss += __shfl_xor_sync(0xffffffffu, ss, o);
    float inv = 1.f / fmaxf(sqrtf(ss), 1e-8f);
#pragma unroll
    for (int i = 0; i < 4; i++) {
        v[i].x *= inv; v[i].y *= inv; v[i].z *= inv; v[i].w *= inv;
        p[lane + 32 * i] = v[i];
    }
}

// ---------------------------------------------------------------------------
// Row inverse-norm only (no write-back of the row): rinv = 1/max(||row||,eps)
// ---------------------------------------------------------------------------
__global__ void rownorm_inv(const float* __restrict__ X, float* __restrict__ rinv, int R)
{
    int row = blockIdx.x * 8 + (threadIdx.x >> 5);
    int lane = threadIdx.x & 31;
    if (row >= R) return;
    const float4* p = (const float4*)(X + (size_t)row * DIM_D);
    float ss = 0.f;
#pragma unroll
    for (int i = 0; i < 4; i++) {
        float4 v = p[lane + 32 * i];
        ss += v.x * v.x + v.y * v.y + v.z * v.z + v.w * v.w;
    }
#pragma unroll
    for (int o = 16; o > 0; o >>= 1) ss += __shfl_xor_sync(0xffffffffu, ss, o);
    if (lane == 0) rinv[row] = 1.f / fmaxf(sqrtf(ss), 1e-8f);
}

// ---------------------------------------------------------------------------
// Transpose step_proto (128 x 512) -> (512 x 128)
// ---------------------------------------------------------------------------
__global__ void transpose_proto(const float* __restrict__ in, float* __restrict__ out)
{
    int idx = blockIdx.x * 256 + threadIdx.x;
    int s = idx >> 9, d = idx & 511;
    out[d * DIM_S + s] = in[idx];
}

// ---------------------------------------------------------------------------
// Warp-synchronous DAG scan. One WARP per batch. Lane l owns states 4l..4l+3.
// Critical path trimmed: e = e^raw (prefetched, off-path) * sqrt(mass)
// (exact for LAM_TOPO=0.5); only the Z-butterfly gates alpha; aux (mass
// sum/max) butterflies deferred to after the alpha store.
// ---------------------------------------------------------------------------
__global__ __launch_bounds__(32) void scan_kernel(
    const float* __restrict__ raw,
    float* __restrict__ alpha_out,
    float* __restrict__ aux)
{
    const unsigned FULL = 0xffffffffu;
    int b = blockIdx.x;
    int l = threadIdx.x;

    int s0 = 4 * l;
    bool h1[4], h2[4], h4[4], h8[4];
    float invc[4];
#pragma unroll
    for (int i = 0; i < 4; i++) {
        int s = s0 + i;
        h1[i] = s >= 1; h2[i] = s >= 2; h4[i] = s >= 4; h8[i] = s >= 8;
        int c = (int)h1[i] + (int)h2[i] + (int)h4[i] + (int)h8[i];
        invc[i] = c ? 1.f / (float)c : 0.f;
    }

    float p[4] = {1.f / DIM_S, 1.f / DIM_S, 1.f / DIM_S, 1.f / DIM_S};

    const float* rp = raw + (size_t)b * DIM_T * DIM_S;
    float* ap = alpha_out + (size_t)b * DIM_T * DIM_S;

    float4 rv = *(const float4*)(rp + s0);
    float ec[4] = {__expf(rv.x), __expf(rv.y), __expf(rv.z), __expf(rv.w)};

    for (int t = 0; t < DIM_T; t++) {
        float ecur[4] = {ec[0], ec[1], ec[2], ec[3]};
        if (t + 1 < DIM_T) {
            rv = *(const float4*)(rp + (size_t)(t + 1) * DIM_S + s0);
            ec[0] = __expf(rv.x); ec[1] = __expf(rv.y);
            ec[2] = __expf(rv.z); ec[3] = __expf(rv.w);
        }

        float u1[4], u2[4];
#pragma unroll
        for (int i = 0; i < 4; i++) {
            u1[i] = __shfl_up_sync(FULL, p[i], 1);
            u2[i] = __shfl_up_sync(FULL, p[i], 2);
        }
        float v1[4] = {u1[3], p[0], p[1], p[2]};
        float v2[4] = {u1[2], u1[3], p[0], p[1]};

        float e[4], m[4];
        float les = 0.f;
#pragma unroll
        for (int i = 0; i < 4; i++) {
            float pm = 0.f, px = -1e30f;
            if (h1[i]) { pm += v1[i]; px = fmaxf(px, v1[i]); }
            if (h2[i]) { pm += v2[i]; px = fmaxf(px, v2[i]); }
            if (h4[i]) { pm += u1[i]; px = fmaxf(px, u1[i]); }
            if (h8[i]) { pm += u2[i]; px = fmaxf(px, u2[i]); }
            float pmean = pm * invc[i];
            float pmax  = h1[i] ? px : 0.f;
            float mass = fmaxf(LAM_SELF * p[i] + LAM_SUCC * pmax + LAM_PRED * pmean, 1e-8f);
            m[i] = mass;
            e[i] = ecur[i] * __fsqrt_rn(mass);   // == exp(raw + 0.5*log(mass))
            les += e[i];
        }

        // Z butterfly — the only reduction gating alpha
#pragma unroll
        for (int o = 16; o > 0; o >>= 1)
            les += __shfl_xor_sync(FULL, les, o);

        float invZ = __fdividef(1.f, les);
        float4 av;
        av.x = e[0] * invZ; av.y = e[1] * invZ;
        av.z = e[2] * invZ; av.w = e[3] * invZ;
        *(float4*)(ap + (size_t)t * DIM_S + s0) = av;
        p[0] = av.x; p[1] = av.y; p[2] = av.z; p[3] = av.w;

        // deferred aux reductions (not on the loop-carried path)
        float lms = m[0] + m[1] + m[2] + m[3];
        float lmm = fmaxf(fmaxf(m[0], m[1]), fmaxf(m[2], m[3]));
#pragma unroll
        for (int o = 16; o > 0; o >>= 1) {
            lms += __shfl_xor_sync(FULL, lms, o);
            lmm = fmaxf(lmm, __shfl_xor_sync(FULL, lmm, o));
        }
        if (l == 0) {
            float* ax = aux + ((size_t)b * DIM_T + t) * 8;
            ax[5] = lms * (1.0f / DIM_S);
            ax[6] = lmm;
        }
    }
}

// ---------------------------------------------------------------------------
// Per-(b,t) row kernel (R13 champion). qerr row is scaled by its inverse
// norm at load (fused normalization).
// ---------------------------------------------------------------------------
__global__ __launch_bounds__(128) void sparse_kernel(
    const float* __restrict__ alpha,    // [NROWS, S]
    const float* __restrict__ qerr,     // [NROWS, D] (UNNORMALIZED)
    const float* __restrict__ rinv,     // [NROWS] inverse norms of qerr rows
    const float* __restrict__ errproto, // [S*M, D]
    float* __restrict__ out)
{
    int row = blockIdx.x;
    int tid = threadIdx.x;
    int lane = tid & 31, w = tid >> 5;

    __shared__ __align__(16) float sh_q[DIM_D];
    __shared__ float warp_vals[4][K_MAX];
    __shared__ int   warp_idx [4][K_MAX];
    __shared__ int   sel_idx[K_MAX];
    __shared__ float sel_alpha[K_MAX];
    __shared__ int   sel_flag[DIM_S];
    __shared__ int   sh_count;
    __shared__ float sh_top1, sh_top2;
    __shared__ float sh_logits[K_MAX][DIM_M];
    __shared__ float sh_beta [K_MAX][DIM_M];
    __shared__ float sh_gamma[K_MAX][DIM_M];
    __shared__ float sh_H[K_MAX];
    __shared__ float sh_gsum_j[K_MAX];
    __shared__ float redA[4], redB[4];

    float a = alpha[(size_t)row * DIM_S + tid];
    sel_flag[tid] = 0;
    {
        float rq = rinv[row];
        float4 qv = ((const float4*)(qerr + (size_t)row * DIM_D))[tid];
        qv.x *= rq; qv.y *= rq; qv.z *= rq; qv.w *= rq;
        ((float4*)sh_q)[tid] = qv;
    }
    __syncthreads();

    // ---- per-warp top-5 (value desc, index asc tiebreak) ----
    {
        float v = a;
        int id = tid;
#pragma unroll
        for (int j = 0; j < K_MAX; j++) {
            float bv = v; int bi = id;
#pragma unroll
            for (int o = 16; o > 0; o >>= 1) {
                float ov = __shfl_xor_sync(0xffffffffu, bv, o);
                int   oi = __shfl_xor_sync(0xffffffffu, bi, o);
                if (ov > bv || (ov == bv && oi < bi)) { bv = ov; bi = oi; }
            }
            if (lane == 0) { warp_vals[w][j] = bv; warp_idx[w][j] = bi; }
            if (id == bi) v = -1e30f;
        }
    }
    __syncthreads();

    // ---- thread 0: merge 20 candidates, apply rho/K_MAX keep rule ----
    if (tid == 0) {
        float vals[20]; int ids[20]; bool used[20];
#pragma unroll
        for (int w2 = 0; w2 < 4; w2++)
#pragma unroll
            for (int j = 0; j < K_MAX; j++) {
                vals[w2 * K_MAX + j] = warp_vals[w2][j];
                ids [w2 * K_MAX + j] = warp_idx [w2][j];
                used[w2 * K_MAX + j] = false;
            }
        float prefix = 0.f, top1 = 0.f, top2 = 0.f;
        int cnt = 0;
        for (int j = 0; j < K_MAX; j++) {
            int best = -1;
            for (int c = 0; c < 20; c++) {
                if (used[c]) continue;
                if (best < 0 || vals[c] > vals[best] ||
                    (vals[c] == vals[best] && ids[c] < ids[best])) best = c;
            }
            used[best] = true;
            if (j == 0) top1 = vals[best];
            if (j == 1) top2 = vals[best];
            bool keep = prefix < RHO_ERR;
            prefix += vals[best];
            if (keep) {
                sel_idx[cnt] = ids[best];
                sel_alpha[cnt] = vals[best];
                sel_flag[ids[best]] = cnt + 1;
                cnt++;
            }
        }
        sh_count = cnt;
        sh_top1 = top1;
        sh_top2 = top2;
    }
    __syncthreads();
    int count = sh_count;

    // ---- cmask ----
    int f = sel_flag[tid];
    out[CMASK_OFF + (size_t)row * DIM_S + tid] = f ? 1.f : 0.f;

    // ---- err logits for selected steps: warp w handles m = 4w..4w+3 ----
    for (int j = 0; j < count; j++) {
        int s = sel_idx[j];
        const float* ep = errproto + (size_t)(s * DIM_M + w * 4) * DIM_D;
#pragma unroll
        for (int mi = 0; mi < 4; mi++) {
            const float4* er = (const float4*)(ep + (size_t)mi * DIM_D);
            float sum = 0.f;
#pragma unroll
            for (int i = 0; i < 4; i++) {
                float4 q = ((const float4*)sh_q)[i * 32 + lane];
                float4 e = er[i * 32 + lane];
                sum += q.x * e.x + q.y * e.y + q.z * e.z + q.w * e.w;
            }
#pragma unroll
            for (int o = 16; o > 0; o >>= 1) sum += __shfl_xor_sync(0xffffffffu, sum, o);
            if (lane == 0) sh_logits[j][w * 4 + mi] = sum * (1.0f / TAU_ERR);
        }
    }
    __syncthreads();

    // ---- beta / gamma / entropy per selected step ----
    if (tid < count) {
        float l[DIM_M];
        float mx = -1e30f;
#pragma unroll
        for (int m = 0; m < DIM_M; m++) { l[m] = sh_logits[tid][m]; mx = fmaxf(mx, l[m]); }
        float sum = 0.f;
#pragma unroll
        for (int m = 0; m < DIM_M; m++) { l[m] = __expf(l[m] - mx); sum += l[m]; }
        float inv = 1.f / sum;
        float as_ = sel_alpha[tid];
        float H = 0.f, gs = 0.f;
#pragma unroll
        for (int m = 0; m < DIM_M; m++) {
            float be = l[m] * inv;
            sh_beta[tid][m] = be;
            float g = as_ * be;
            sh_gamma[tid][m] = g;
            gs += g;
            H -= be * __logf(fmaxf(be, 1e-8f));
        }
        sh_H[tid] = H;
        sh_gsum_j[tid] = gs;
    }
    __syncthreads();

    // ---- coalesced beta & gamma writes: thread -> float4 index q*128+tid ----
    {
        float4* brow = (float4*)(out + BETA_OFF  + (size_t)row * (DIM_S * DIM_M));
        float4* grow = (float4*)(out + GAMMA_OFF + (size_t)row * (DIM_S * DIM_M));
#pragma unroll
        for (int q = 0; q < 4; q++) {
            int fi = q * 128 + tid;
            int s  = fi >> 2;
            int m0 = (fi & 3) << 2;
            int fj = sel_flag[s];
            float4 bv, gv;
            if (fj) {
                int j = fj - 1;
                bv = make_float4(sh_beta[j][m0], sh_beta[j][m0+1],
                                 sh_beta[j][m0+2], sh_beta[j][m0+3]);
                gv = make_float4(sh_gamma[j][m0], sh_gamma[j][m0+1],
                                 sh_gamma[j][m0+2], sh_gamma[j][m0+3]);
            } else {
                bv = make_float4(0.0625f, 0.0625f, 0.0625f, 0.0625f);
                gv = make_float4(0.f, 0.f, 0.f, 0.f);
            }
            brow[fi] = bv;
            grow[fi] = gv;
        }
    }

    // ---- err_sem_obs: thread handles d = tid*4 .. tid*4+3 ----
    {
        float4 acc = make_float4(0.f, 0.f, 0.f, 0.f);
        for (int j = 0; j < count; j++) {
            int s = sel_idx[j];
            const float* base = errproto + (size_t)s * DIM_M * DIM_D + tid * 4;
#pragma unroll
            for (int m = 0; m < DIM_M; m++) {
                float g = sh_gamma[j][m];
                float4 e = *(const float4*)(base + (size_t)m * DIM_D);
                acc.x += g * e.x; acc.y += g * e.y; acc.z += g * e.z; acc.w += g * e.w;
            }
        }
        *(float4*)(out + ERRO_OFF + (size_t)row * DIM_D + tid * 4) = acc;
    }

    // ---- aux reductions: alpha entropy, sum(H(beta)*alpha) ----
    {
        float ent = -a * __logf(fmaxf(a, 1e-8f));
        float ht = (f ? sh_H[f - 1] : LOG16) * a;
#pragma unroll
        for (int o = 16; o > 0; o >>= 1) {
            ent += __shfl_xor_sync(0xffffffffu, ent, o);
            ht  += __shfl_xor_sync(0xffffffffu, ht, o);
        }
        if (lane == 0) { redA[w] = ent; redB[w] = ht; }
        __syncthreads();
        if (tid == 0) {
            float entropy = redA[0] + redA[1] + redA[2] + redA[3];
            float hsum    = redB[0] + redB[1] + redB[2] + redB[3];
            float gsum = 0.f;
            for (int j = 0; j < count; j++) gsum += sh_gsum_j[j];
            float* ax = out + AUX_OFF + (size_t)row * 8;
            ax[0] = entropy;
            ax[1] = sh_top1;
            ax[2] = sh_top1 - sh_top2;
            ax[3] = gsum;
            ax[4] = hsum;
            ax[7] = (float)count / (float)K_MAX;
        }
    }
}

// ---------------------------------------------------------------------------
// Launch (qstep GEMM at index 3 = the profiled slot, as control)
// ---------------------------------------------------------------------------
extern "C" void kernel_launch(void* const* d_in, const int* in_sizes, int n_in,
                              void* d_out, int out_size)
{
    (void)in_sizes; (void)n_in; (void)out_size;
    const float* frame   = (const float*)d_in[0];
    const float* stepp   = (const float*)d_in[1];
    const float* errp    = (const float*)d_in[2];
    const float* Wq_step = (const float*)d_in[3];
    const float* bq_step = (const float*)d_in[4];
    const float* Wq_err  = (const float*)d_in[5];
    const float* bq_err  = (const float*)d_in[6];
    const float* Wa_step = (const float*)d_in[7];
    const float* ba_step = (const float*)d_in[8];
    const float* Wa_err  = (const float*)d_in[9];
    const float* ba_err  = (const float*)d_in[10];
    float* out = (float*)d_out;

    float *qstep, *qerr, *sproto, *sprotoT, *eproto, *rq, *re;
    cudaGetSymbolAddress((void**)&qstep,   g_qstep);
    cudaGetSymbolAddress((void**)&qerr,    g_qerr);
    cudaGetSymbolAddress((void**)&sproto,  g_stepproto);
    cudaGetSymbolAddress((void**)&sprotoT, g_stepprotoT);
    cudaGetSymbolAddress((void**)&eproto,  g_errproto);
    cudaGetSymbolAddress((void**)&rq,      g_rinv_qstep);
    cudaGetSymbolAddress((void**)&re,      g_rinv_qerr);

    // 0: step-proto projection (fully normalized in memory — it's a GEMM operand)
    mma_nt<64, 128, 32, 64><<<dim3(DIM_D / 128, DIM_S / 64), 128>>>(
        stepp, Wa_step, ba_step, nullptr, sproto, DIM_S, DIM_D, DIM_D, 1.f);
    // 1
    normalize_rows<<<DIM_S / 4, 128>>>(sproto, DIM_S);
    // 2
    transpose_proto<<<(DIM_S * DIM_D) / 256, 256>>>(sproto, sprotoT);
    // 3: qstep projection (UNNORMALIZED) <-- profiled slot
    mma_nt<128, 128, 32, 64><<<dim3(DIM_D / 128, NROWS / 128), 256>>>(
        frame, Wq_step, bq_step, nullptr, qstep, NROWS, DIM_D, DIM_D, 1.f);
    // 4: row inverse norms of qstep
    rownorm_inv<<<NROWS / 8, 256>>>(qstep, rq, NROWS);
    // 5: err-proto projection (normalized in memory — used as data twice)
    mma_nt<128, 128, 32, 64><<<dim3(DIM_D / 128, ERR_ROWS / 128), 256>>>(
        errp, Wa_err, ba_err, nullptr, eproto, ERR_ROWS, DIM_D, DIM_D, 1.f);
    // 6
    normalize_rows<<<ERR_ROWS / 4, 128>>>(eproto, ERR_ROWS);
    // 7: qerr projection (UNNORMALIZED)
    mma_nt<128, 128, 32, 64><<<dim3(DIM_D / 128, NROWS / 128), 256>>>(
        frame, Wq_err, bq_err, nullptr, qerr, NROWS, DIM_D, DIM_D, 1.f);
    // 8: row inverse norms of qerr
    rownorm_inv<<<NROWS / 8, 256>>>(qerr, re, NROWS);
    // 9: raw_step_logits = rowscale * (qstep @ sproto^T) / tau  (norm fused)
    mma_nt<64, 128, 32, 64><<<dim3(DIM_S / 128, NROWS / 64), 128>>>(
        qstep, sproto, nullptr, rq, out + RAW_OFF, NROWS, DIM_S, DIM_D, 1.f / TAU_STEP);
    // 10: warp-synchronous DAG scan
    scan_kernel<<<DIM_B, 32>>>(out + RAW_OFF, out + ALPHA_OFF, out + AUX_OFF);
    // 11: sparse error path (qerr norm fused at sh_q load)
    sparse_kernel<<<NROWS, 128>>>(out + ALPHA_OFF, qerr, re, eproto, out);
    // 12: step_sem_obs = alpha @ step_proto
    mma_nt<128, 128, 32, 64><<<dim3(DIM_D / 128, NROWS / 128), 256>>>(
        out + ALPHA_OFF, sprotoT, nullptr, nullptr, out + STEP_OFF, NROWS, DIM_D, DIM_S, 1.f);
}

// round 16
// speedup vs baseline: 1.2182x; 1.2182x over previous
#include <cuda_runtime.h>
#include <cuda_bf16.h>
#include <math.h>
#include <stdint.h>
#include <cstdint>

// ---------------------------------------------------------------------------
// Problem dims (fixed)
// ---------------------------------------------------------------------------
#define DIM_B 16
#define DIM_T 512
#define DIM_S 128
#define DIM_M 16
#define DIM_D 512
#define NROWS (DIM_B * DIM_T)        // 8192
#define ERR_ROWS (DIM_S * DIM_M)     // 2048

#define TAU_STEP 0.07f
#define TAU_ERR  0.07f
#define RHO_ERR  0.85f
#define K_MAX    5
#define LAM_SELF 1.0f
#define LAM_SUCC 0.8f
#define LAM_PRED 0.4f
#define LAM_TOPO 0.5f
#define LOG16    2.772588722239781f

// Output layout (floats), in reference tuple order
#define ALPHA_OFF 0
#define GAMMA_OFF (ALPHA_OFF + NROWS * DIM_S)
#define BETA_OFF  (GAMMA_OFF + NROWS * DIM_S * DIM_M)
#define STEP_OFF  (BETA_OFF  + NROWS * DIM_S * DIM_M)
#define ERRO_OFF  (STEP_OFF  + NROWS * DIM_D)
#define AUX_OFF   (ERRO_OFF  + NROWS * DIM_D)
#define CMASK_OFF (AUX_OFF   + NROWS * 8)
#define RAW_OFF   (CMASK_OFF + NROWS * DIM_S)

// ---------------------------------------------------------------------------
// Scratch (static device globals: allocation-free)
// ---------------------------------------------------------------------------
__device__ float g_qstep[NROWS * DIM_D];
__device__ float g_qerr [NROWS * DIM_D];
__device__ float g_stepproto [DIM_S * DIM_D];
__device__ float g_stepprotoT[DIM_D * DIM_S];
__device__ float g_errproto[ERR_ROWS * DIM_D];
__device__ float g_rinv_qstep[NROWS];
__device__ float g_rinv_qerr [NROWS];

// ---------------------------------------------------------------------------
// TF32 helpers
// ---------------------------------------------------------------------------
__device__ __forceinline__ void split_tf32(float x, uint32_t& hi, uint32_t& lo) {
    uint32_t h = __float_as_uint(x) & 0xFFFFE000u;
    hi = h;
    lo = __float_as_uint(x - __uint_as_float(h));
}

__device__ __forceinline__ void mma_m16n8k8(float* c, const uint32_t* a, const uint32_t* b) {
    asm volatile(
        "mma.sync.aligned.m16n8k8.row.col.f32.tf32.tf32.f32 "
        "{%0,%1,%2,%3}, {%4,%5,%6,%7}, {%8,%9}, {%0,%1,%2,%3};\n"
        : "+f"(c[0]), "+f"(c[1]), "+f"(c[2]), "+f"(c[3])
        : "r"(a[0]), "r"(a[1]), "r"(a[2]), "r"(a[3]), "r"(b[0]), "r"(b[1]));
}

// ---------------------------------------------------------------------------
// TF32 (3x split) GEMM NT (R9 champion inner loop) with optional per-row
// output scale: C[m,n] = scale * rowscale[m] * (sum_k A[m,k]*B[n,k] + bias[n])
// ---------------------------------------------------------------------------
template<int BM, int BN, int WM, int WN>
__global__ void __launch_bounds__((BM / WM) * (BN / WN) * 32)
mma_nt(const float* __restrict__ A, const float* __restrict__ B,
       const float* __restrict__ bias, const float* __restrict__ rowscale,
       float* __restrict__ C, int M, int N, int K, float scale)
{
    constexpr int WARPS_M = BM / WM;
    constexpr int WARPS_N = BN / WN;
    constexpr int NTHREADS = WARPS_M * WARPS_N * 32;
    constexpr int FM = WM / 16;
    constexpr int FN = WN / 8;
    constexpr int LDA = 20;
    constexpr int LA = BM * 4 / NTHREADS;
    constexpr int LB = BN * 4 / NTHREADS;

    __shared__ __align__(16) float sA[2][BM * LDA];
    __shared__ __align__(16) float sB[2][BN * LDA];

    const int tid = threadIdx.x;
    const int lane = tid & 31;
    const int warp = tid >> 5;
    const int gid = lane >> 2, tig = lane & 3;
    const int wm0 = (warp % WARPS_M) * WM;
    const int wn0 = (warp / WARPS_M) * WN;
    const int bm = blockIdx.y * BM;
    const int bn = blockIdx.x * BN;

    float acc[FM][FN][4];
#pragma unroll
    for (int i = 0; i < FM; i++)
#pragma unroll
        for (int j = 0; j < FN; j++)
#pragma unroll
            for (int q = 0; q < 4; q++) acc[i][j][q] = 0.f;

    float4 stageA[LA], stageB[LB];

    auto gload = [&](int kt) {
        int k0 = kt * 16;
#pragma unroll
        for (int i = 0; i < LA; i++) {
            int c = tid + i * NTHREADS;
            int row = c >> 2, kc = (c & 3) << 2;
            stageA[i] = *(const float4*)(A + (size_t)(bm + row) * K + k0 + kc);
        }
#pragma unroll
        for (int i = 0; i < LB; i++) {
            int c = tid + i * NTHREADS;
            int row = c >> 2, kc = (c & 3) << 2;
            stageB[i] = *(const float4*)(B + (size_t)(bn + row) * K + k0 + kc);
        }
    };

    auto sstore = [&](int buf) {
#pragma unroll
        for (int i = 0; i < LA; i++) {
            int c = tid + i * NTHREADS;
            int row = c >> 2, kc = (c & 3) << 2;
            *(float4*)(&sA[buf][row * LDA + kc]) = stageA[i];
        }
#pragma unroll
        for (int i = 0; i < LB; i++) {
            int c = tid + i * NTHREADS;
            int row = c >> 2, kc = (c & 3) << 2;
            *(float4*)(&sB[buf][row * LDA + kc]) = stageB[i];
        }
    };

    const int KT = K >> 4;
    gload(0);
    sstore(0);
    __syncthreads();

    int buf = 0;
    for (int kt = 0; kt < KT; kt++) {
        if (kt + 1 < KT) gload(kt + 1);

#pragma unroll
        for (int ks = 0; ks < 2; ks++) {
            uint32_t ahi[FM][4], alo[FM][4];
#pragma unroll
            for (int fm = 0; fm < FM; fm++) {
                int r = wm0 + fm * 16 + gid;
                float x0 = sA[buf][r * LDA + ks * 8 + tig];
                float x1 = sA[buf][(r + 8) * LDA + ks * 8 + tig];
                float x2 = sA[buf][r * LDA + ks * 8 + tig + 4];
                float x3 = sA[buf][(r + 8) * LDA + ks * 8 + tig + 4];
                split_tf32(x0, ahi[fm][0], alo[fm][0]);
                split_tf32(x1, ahi[fm][1], alo[fm][1]);
                split_tf32(x2, ahi[fm][2], alo[fm][2]);
                split_tf32(x3, ahi[fm][3], alo[fm][3]);
            }
#pragma unroll
            for (int fn = 0; fn < FN; fn++) {
                int n = wn0 + fn * 8 + gid;
                float y0 = sB[buf][n * LDA + ks * 8 + tig];
                float y1 = sB[buf][n * LDA + ks * 8 + tig + 4];
                uint32_t bhi[2], blo[2];
                split_tf32(y0, bhi[0], blo[0]);
                split_tf32(y1, bhi[1], blo[1]);
#pragma unroll
                for (int fm = 0; fm < FM; fm++) {
                    mma_m16n8k8(acc[fm][fn], alo[fm], bhi);
                    mma_m16n8k8(acc[fm][fn], ahi[fm], blo);
                    mma_m16n8k8(acc[fm][fn], ahi[fm], bhi);
                }
            }
        }

        if (kt + 1 < KT) sstore(buf ^ 1);
        __syncthreads();
        buf ^= 1;
    }

#pragma unroll
    for (int fm = 0; fm < FM; fm++) {
        int r0 = bm + wm0 + fm * 16 + gid;
        float rs0 = scale, rs1 = scale;
        if (rowscale) { rs0 *= rowscale[r0]; rs1 *= rowscale[r0 + 8]; }
#pragma unroll
        for (int fn = 0; fn < FN; fn++) {
            int c0 = bn + wn0 + fn * 8 + 2 * tig;
            float bx = 0.f, by = 0.f;
            if (bias) { bx = bias[c0]; by = bias[c0 + 1]; }
            float2 v0, v1;
            v0.x = (acc[fm][fn][0] + bx) * rs0;
            v0.y = (acc[fm][fn][1] + by) * rs0;
            v1.x = (acc[fm][fn][2] + bx) * rs1;
            v1.y = (acc[fm][fn][3] + by) * rs1;
            *(float2*)(C + (size_t)r0 * N + c0) = v0;
            *(float2*)(C + (size_t)(r0 + 8) * N + c0) = v1;
        }
    }
}

// ---------------------------------------------------------------------------
// Row-wise L2 normalize (in place), width 512. One warp per row.
// ---------------------------------------------------------------------------
__global__ void normalize_rows(float* __restrict__ X, int R)
{
    int row = blockIdx.x * 4 + (threadIdx.x >> 5);
    int lane = threadIdx.x & 31;
    if (row >= R) return;
    float4* p = (float4*)(X + (size_t)row * DIM_D);
    float4 v[4];
    float ss = 0.f;
#pragma unroll
    for (int i = 0; i < 4; i++) {
        v[i] = p[lane + 32 * i];
        ss += v[i].x * v[i].x + v[i].y * v[i].y + v[i].z * v[i].z + v[i].w * v[i].w;
    }
#pragma unroll
    for (int o = 16; o > 0; o >>= 1) ss += __shfl_xor_sync(0xffffffffu, ss, o);
    float inv = 1.f / fmaxf(sqrtf(ss), 1e-8f);
#pragma unroll
    for (int i = 0; i < 4; i++) {
        v[i].x *= inv; v[i].y *= inv; v[i].z *= inv; v[i].w *= inv;
        p[lane + 32 * i] = v[i];
    }
}

// ---------------------------------------------------------------------------
// Row inverse-norm only: rinv = 1/max(||row||,eps). One warp per row.
// ---------------------------------------------------------------------------
__global__ void rownorm_inv(const float* __restrict__ X, float* __restrict__ rinv, int R)
{
    int row = blockIdx.x * 8 + (threadIdx.x >> 5);
    int lane = threadIdx.x & 31;
    if (row >= R) return;
    const float4* p = (const float4*)(X + (size_t)row * DIM_D);
    float ss = 0.f;
#pragma unroll
    for (int i = 0; i < 4; i++) {
        float4 v = p[lane + 32 * i];
        ss += v.x * v.x + v.y * v.y + v.z * v.z + v.w * v.w;
    }
#pragma unroll
    for (int o = 16; o > 0; o >>= 1) ss += __shfl_xor_sync(0xffffffffu, ss, o);
    if (lane == 0) rinv[row] = 1.f / fmaxf(sqrtf(ss), 1e-8f);
}

// ---------------------------------------------------------------------------
// Transpose step_proto (128 x 512) -> (512 x 128)
// ---------------------------------------------------------------------------
__global__ void transpose_proto(const float* __restrict__ in, float* __restrict__ out)
{
    int idx = blockIdx.x * 256 + threadIdx.x;
    int s = idx >> 9, d = idx & 511;
    out[d * DIM_S + s] = in[idx];
}

// ---------------------------------------------------------------------------
// Warp-synchronous DAG scan — R9 VERSION VERBATIM (measured good).
// One WARP per batch b. Lane l owns states 4l..4l+3. Max-free softmax.
// ---------------------------------------------------------------------------
__global__ __launch_bounds__(32) void scan_kernel(
    const float* __restrict__ raw,
    float* __restrict__ alpha_out,
    float* __restrict__ aux)
{
    const unsigned FULL = 0xffffffffu;
    int b = blockIdx.x;
    int l = threadIdx.x;

    int s0 = 4 * l;
    bool h1[4], h2[4], h4[4], h8[4];
    float invc[4];
#pragma unroll
    for (int i = 0; i < 4; i++) {
        int s = s0 + i;
        h1[i] = s >= 1; h2[i] = s >= 2; h4[i] = s >= 4; h8[i] = s >= 8;
        int c = (int)h1[i] + (int)h2[i] + (int)h4[i] + (int)h8[i];
        invc[i] = c ? 1.f / (float)c : 0.f;
    }

    float p[4] = {1.f / DIM_S, 1.f / DIM_S, 1.f / DIM_S, 1.f / DIM_S};

    const float* rp = raw + (size_t)b * DIM_T * DIM_S;
    float* ap = alpha_out + (size_t)b * DIM_T * DIM_S;
    float4 rv = *(const float4*)(rp + s0);

    for (int t = 0; t < DIM_T; t++) {
        float4 cur = rv;
        if (t + 1 < DIM_T) rv = *(const float4*)(rp + (size_t)(t + 1) * DIM_S + s0);
        float craw[4] = {cur.x, cur.y, cur.z, cur.w};

        float u1[4], u2[4];
#pragma unroll
        for (int i = 0; i < 4; i++) {
            u1[i] = __shfl_up_sync(FULL, p[i], 1);
            u2[i] = __shfl_up_sync(FULL, p[i], 2);
        }
        float v1[4] = {u1[3], p[0], p[1], p[2]};
        float v2[4] = {u1[2], u1[3], p[0], p[1]};

        float e[4];
        float les = 0.f, lms = 0.f, lmm = -1e30f;
#pragma unroll
        for (int i = 0; i < 4; i++) {
            float pm = 0.f, px = -1e30f;
            if (h1[i]) { pm += v1[i]; px = fmaxf(px, v1[i]); }
            if (h2[i]) { pm += v2[i]; px = fmaxf(px, v2[i]); }
            if (h4[i]) { pm += u1[i]; px = fmaxf(px, u1[i]); }
            if (h8[i]) { pm += u2[i]; px = fmaxf(px, u2[i]); }
            float pmean = pm * invc[i];
            float pmax  = h1[i] ? px : 0.f;
            float mass = fmaxf(LAM_SELF * p[i] + LAM_SUCC * pmax + LAM_PRED * pmean, 1e-8f);
            float logit = craw[i] + LAM_TOPO * __logf(mass);
            e[i] = __expf(logit);         // max-free: |logit| < 24, no overflow
            les += e[i];
            lms += mass;
            lmm = fmaxf(lmm, mass);
        }

#pragma unroll
        for (int o = 16; o > 0; o >>= 1) {
            les += __shfl_xor_sync(FULL, les, o);
            lms += __shfl_xor_sync(FULL, lms, o);
            lmm = fmaxf(lmm, __shfl_xor_sync(FULL, lmm, o));
        }

        float invZ = __fdividef(1.f, les);
        float4 av;
        av.x = e[0] * invZ; av.y = e[1] * invZ;
        av.z = e[2] * invZ; av.w = e[3] * invZ;
        *(float4*)(ap + (size_t)t * DIM_S + s0) = av;
        p[0] = av.x; p[1] = av.y; p[2] = av.z; p[3] = av.w;

        if (l == 0) {
            float* ax = aux + ((size_t)b * DIM_T + t) * 8;
            ax[5] = lms * (1.0f / DIM_S);
            ax[6] = lmm;
        }
    }
}

// ---------------------------------------------------------------------------
// Per-(b,t) row kernel (R13 champion). qerr row scaled by inverse norm at
// load (fused normalization).
// ---------------------------------------------------------------------------
__global__ __launch_bounds__(128) void sparse_kernel(
    const float* __restrict__ alpha,    // [NROWS, S]
    const float* __restrict__ qerr,     // [NROWS, D] (UNNORMALIZED)
    const float* __restrict__ rinv,     // [NROWS] inverse norms of qerr rows
    const float* __restrict__ errproto, // [S*M, D]
    float* __restrict__ out)
{
    int row = blockIdx.x;
    int tid = threadIdx.x;
    int lane = tid & 31, w = tid >> 5;

    __shared__ __align__(16) float sh_q[DIM_D];
    __shared__ float warp_vals[4][K_MAX];
    __shared__ int   warp_idx [4][K_MAX];
    __shared__ int   sel_idx[K_MAX];
    __shared__ float sel_alpha[K_MAX];
    __shared__ int   sel_flag[DIM_S];
    __shared__ int   sh_count;
    __shared__ float sh_top1, sh_top2;
    __shared__ float sh_logits[K_MAX][DIM_M];
    __shared__ float sh_beta [K_MAX][DIM_M];
    __shared__ float sh_gamma[K_MAX][DIM_M];
    __shared__ float sh_H[K_MAX];
    __shared__ float sh_gsum_j[K_MAX];
    __shared__ float redA[4], redB[4];

    float a = alpha[(size_t)row * DIM_S + tid];
    sel_flag[tid] = 0;
    {
        float rq = rinv[row];
        float4 qv = ((const float4*)(qerr + (size_t)row * DIM_D))[tid];
        qv.x *= rq; qv.y *= rq; qv.z *= rq; qv.w *= rq;
        ((float4*)sh_q)[tid] = qv;
    }
    __syncthreads();

    // ---- per-warp top-5 (value desc, index asc tiebreak) ----
    {
        float v = a;
        int id = tid;
#pragma unroll
        for (int j = 0; j < K_MAX; j++) {
            float bv = v; int bi = id;
#pragma unroll
            for (int o = 16; o > 0; o >>= 1) {
                float ov = __shfl_xor_sync(0xffffffffu, bv, o);
                int   oi = __shfl_xor_sync(0xffffffffu, bi, o);
                if (ov > bv || (ov == bv && oi < bi)) { bv = ov; bi = oi; }
            }
            if (lane == 0) { warp_vals[w][j] = bv; warp_idx[w][j] = bi; }
            if (id == bi) v = -1e30f;
        }
    }
    __syncthreads();

    // ---- thread 0: merge 20 candidates, apply rho/K_MAX keep rule ----
    if (tid == 0) {
        float vals[20]; int ids[20]; bool used[20];
#pragma unroll
        for (int w2 = 0; w2 < 4; w2++)
#pragma unroll
            for (int j = 0; j < K_MAX; j++) {
                vals[w2 * K_MAX + j] = warp_vals[w2][j];
                ids [w2 * K_MAX + j] = warp_idx [w2][j];
                used[w2 * K_MAX + j] = false;
            }
        float prefix = 0.f, top1 = 0.f, top2 = 0.f;
        int cnt = 0;
        for (int j = 0; j < K_MAX; j++) {
            int best = -1;
            for (int c = 0; c < 20; c++) {
                if (used[c]) continue;
                if (best < 0 || vals[c] > vals[best] ||
                    (vals[c] == vals[best] && ids[c] < ids[best])) best = c;
            }
            used[best] = true;
            if (j == 0) top1 = vals[best];
            if (j == 1) top2 = vals[best];
            bool keep = prefix < RHO_ERR;
            prefix += vals[best];
            if (keep) {
                sel_idx[cnt] = ids[best];
                sel_alpha[cnt] = vals[best];
                sel_flag[ids[best]] = cnt + 1;
                cnt++;
            }
        }
        sh_count = cnt;
        sh_top1 = top1;
        sh_top2 = top2;
    }
    __syncthreads();
    int count = sh_count;

    // ---- cmask ----
    int f = sel_flag[tid];
    out[CMASK_OFF + (size_t)row * DIM_S + tid] = f ? 1.f : 0.f;

    // ---- err logits for selected steps: warp w handles m = 4w..4w+3 ----
    for (int j = 0; j < count; j++) {
        int s = sel_idx[j];
        const float* ep = errproto + (size_t)(s * DIM_M + w * 4) * DIM_D;
#pragma unroll
        for (int mi = 0; mi < 4; mi++) {
            const float4* er = (const float4*)(ep + (size_t)mi * DIM_D);
            float sum = 0.f;
#pragma unroll
            for (int i = 0; i < 4; i++) {
                float4 q = ((const float4*)sh_q)[i * 32 + lane];
                float4 e = er[i * 32 + lane];
                sum += q.x * e.x + q.y * e.y + q.z * e.z + q.w * e.w;
            }
#pragma unroll
            for (int o = 16; o > 0; o >>= 1) sum += __shfl_xor_sync(0xffffffffu, sum, o);
            if (lane == 0) sh_logits[j][w * 4 + mi] = sum * (1.0f / TAU_ERR);
        }
    }
    __syncthreads();

    // ---- beta / gamma / entropy per selected step ----
    if (tid < count) {
        float l[DIM_M];
        float mx = -1e30f;
#pragma unroll
        for (int m = 0; m < DIM_M; m++) { l[m] = sh_logits[tid][m]; mx = fmaxf(mx, l[m]); }
        float sum = 0.f;
#pragma unroll
        for (int m = 0; m < DIM_M; m++) { l[m] = __expf(l[m] - mx); sum += l[m]; }
        float inv = 1.f / sum;
        float as_ = sel_alpha[tid];
        float H = 0.f, gs = 0.f;
#pragma unroll
        for (int m = 0; m < DIM_M; m++) {
            float be = l[m] * inv;
            sh_beta[tid][m] = be;
            float g = as_ * be;
            sh_gamma[tid][m] = g;
            gs += g;
            H -= be * __logf(fmaxf(be, 1e-8f));
        }
        sh_H[tid] = H;
        sh_gsum_j[tid] = gs;
    }
    __syncthreads();

    // ---- coalesced beta & gamma writes: thread -> float4 index q*128+tid ----
    {
        float4* brow = (float4*)(out + BETA_OFF  + (size_t)row * (DIM_S * DIM_M));
        float4* grow = (float4*)(out + GAMMA_OFF + (size_t)row * (DIM_S * DIM_M));
#pragma unroll
        for (int q = 0; q < 4; q++) {
            int fi = q * 128 + tid;
            int s  = fi >> 2;
            int m0 = (fi & 3) << 2;
            int fj = sel_flag[s];
            float4 bv, gv;
            if (fj) {
                int j = fj - 1;
                bv = make_float4(sh_beta[j][m0], sh_beta[j][m0+1],
                                 sh_beta[j][m0+2], sh_beta[j][m0+3]);
                gv = make_float4(sh_gamma[j][m0], sh_gamma[j][m0+1],
                                 sh_gamma[j][m0+2], sh_gamma[j][m0+3]);
            } else {
                bv = make_float4(0.0625f, 0.0625f, 0.0625f, 0.0625f);
                gv = make_float4(0.f, 0.f, 0.f, 0.f);
            }
            brow[fi] = bv;
            grow[fi] = gv;
        }
    }

    // ---- err_sem_obs: thread handles d = tid*4 .. tid*4+3 ----
    {
        float4 acc = make_float4(0.f, 0.f, 0.f, 0.f);
        for (int j = 0; j < count; j++) {
            int s = sel_idx[j];
            const float* base = errproto + (size_t)s * DIM_M * DIM_D + tid * 4;
#pragma unroll
            for (int m = 0; m < DIM_M; m++) {
                float g = sh_gamma[j][m];
                float4 e = *(const float4*)(base + (size_t)m * DIM_D);
                acc.x += g * e.x; acc.y += g * e.y; acc.z += g * e.z; acc.w += g * e.w;
            }
        }
        *(float4*)(out + ERRO_OFF + (size_t)row * DIM_D + tid * 4) = acc;
    }

    // ---- aux reductions: alpha entropy, sum(H(beta)*alpha) ----
    {
        float ent = -a * __logf(fmaxf(a, 1e-8f));
        float ht = (f ? sh_H[f - 1] : LOG16) * a;
#pragma unroll
        for (int o = 16; o > 0; o >>= 1) {
            ent += __shfl_xor_sync(0xffffffffu, ent, o);
            ht  += __shfl_xor_sync(0xffffffffu, ht, o);
        }
        if (lane == 0) { redA[w] = ent; redB[w] = ht; }
        __syncthreads();
        if (tid == 0) {
            float entropy = redA[0] + redA[1] + redA[2] + redA[3];
            float hsum    = redB[0] + redB[1] + redB[2] + redB[3];
            float gsum = 0.f;
            for (int j = 0; j < count; j++) gsum += sh_gsum_j[j];
            float* ax = out + AUX_OFF + (size_t)row * 8;
            ax[0] = entropy;
            ax[1] = sh_top1;
            ax[2] = sh_top1 - sh_top2;
            ax[3] = gsum;
            ax[4] = hsum;
            ax[7] = (float)count / (float)K_MAX;
        }
    }
}

// ---------------------------------------------------------------------------
// Launch (qstep GEMM at index 3 = the profiled slot, as control)
// ---------------------------------------------------------------------------
extern "C" void kernel_launch(void* const* d_in, const int* in_sizes, int n_in,
                              void* d_out, int out_size)
{
    (void)in_sizes; (void)n_in; (void)out_size;
    const float* frame   = (const float*)d_in[0];
    const float* stepp   = (const float*)d_in[1];
    const float* errp    = (const float*)d_in[2];
    const float* Wq_step = (const float*)d_in[3];
    const float* bq_step = (const float*)d_in[4];
    const float* Wq_err  = (const float*)d_in[5];
    const float* bq_err  = (const float*)d_in[6];
    const float* Wa_step = (const float*)d_in[7];
    const float* ba_step = (const float*)d_in[8];
    const float* Wa_err  = (const float*)d_in[9];
    const float* ba_err  = (const float*)d_in[10];
    float* out = (float*)d_out;

    float *qstep, *qerr, *sproto, *sprotoT, *eproto, *rq, *re;
    cudaGetSymbolAddress((void**)&qstep,   g_qstep);
    cudaGetSymbolAddress((void**)&qerr,    g_qerr);
    cudaGetSymbolAddress((void**)&sproto,  g_stepproto);
    cudaGetSymbolAddress((void**)&sprotoT, g_stepprotoT);
    cudaGetSymbolAddress((void**)&eproto,  g_errproto);
    cudaGetSymbolAddress((void**)&rq,      g_rinv_qstep);
    cudaGetSymbolAddress((void**)&re,      g_rinv_qerr);

    // 0: step-proto projection (normalized in memory — GEMM operand)
    mma_nt<64, 128, 32, 64><<<dim3(DIM_D / 128, DIM_S / 64), 128>>>(
        stepp, Wa_step, ba_step, nullptr, sproto, DIM_S, DIM_D, DIM_D, 1.f);
    // 1
    normalize_rows<<<DIM_S / 4, 128>>>(sproto, DIM_S);
    // 2
    transpose_proto<<<(DIM_S * DIM_D) / 256, 256>>>(sproto, sprotoT);
    // 3: qstep projection (UNNORMALIZED) <-- profiled slot (control)
    mma_nt<128, 128, 32, 64><<<dim3(DIM_D / 128, NROWS / 128), 256>>>(
        frame, Wq_step, bq_step, nullptr, qstep, NROWS, DIM_D, DIM_D, 1.f);
    // 4: row inverse norms of qstep
    rownorm_inv<<<NROWS / 8, 256>>>(qstep, rq, NROWS);
    // 5: err-proto projection (normalized in memory — used as data twice)
    mma_nt<128, 128, 32, 64><<<dim3(DIM_D / 128, ERR_ROWS / 128), 256>>>(
        errp, Wa_err, ba_err, nullptr, eproto, ERR_ROWS, DIM_D, DIM_D, 1.f);
    // 6
    normalize_rows<<<ERR_ROWS / 4, 128>>>(eproto, ERR_ROWS);
    // 7: qerr projection (UNNORMALIZED)
    mma_nt<128, 128, 32, 64><<<dim3(DIM_D / 128, NROWS / 128), 256>>>(
        frame, Wq_err, bq_err, nullptr, qerr, NROWS, DIM_D, DIM_D, 1.f);
    // 8: row inverse norms of qerr
    rownorm_inv<<<NROWS / 8, 256>>>(qerr, re, NROWS);
    // 9: raw_step_logits = rowscale * (qstep @ sproto^T) / tau  (norm fused)
    mma_nt<64, 128, 32, 64><<<dim3(DIM_S / 128, NROWS / 64), 128>>>(
        qstep, sproto, nullptr, rq, out + RAW_OFF, NROWS, DIM_S, DIM_D, 1.f / TAU_STEP);
    // 10: warp-synchronous DAG scan (R9 verbatim)
    scan_kernel<<<DIM_B, 32>>>(out + RAW_OFF, out + ALPHA_OFF, out + AUX_OFF);
    // 11: sparse error path (qerr norm fused at sh_q load)
    sparse_kernel<<<NROWS, 128>>>(out + ALPHA_OFF, qerr, re, eproto, out);
    // 12: step_sem_obs = alpha @ step_proto
    mma_nt<128, 128, 32, 64><<<dim3(DIM_D / 128, NROWS / 128), 256>>>(
        out + ALPHA_OFF, sprotoT, nullptr, nullptr, out + STEP_OFF, NROWS, DIM_D, DIM_S, 1.f);
}

// round 17
// speedup vs baseline: 1.3481x; 1.1066x over previous
#include <cuda_runtime.h>
#include <cuda_bf16.h>
#include <math.h>
#include <stdint.h>
#include <cstdint>

// ---------------------------------------------------------------------------
// Problem dims (fixed)
// ---------------------------------------------------------------------------
#define DIM_B 16
#define DIM_T 512
#define DIM_S 128
#define DIM_M 16
#define DIM_D 512
#define NROWS (DIM_B * DIM_T)        // 8192
#define ERR_ROWS (DIM_S * DIM_M)     // 2048

#define TAU_STEP 0.07f
#define TAU_ERR  0.07f
#define RHO_ERR  0.85f
#define K_MAX    5
#define LAM_SELF 1.0f
#define LAM_SUCC 0.8f
#define LAM_PRED 0.4f
#define LAM_TOPO 0.5f
#define LOG16    2.772588722239781f

// Output layout (floats), in reference tuple order
#define ALPHA_OFF 0
#define GAMMA_OFF (ALPHA_OFF + NROWS * DIM_S)
#define BETA_OFF  (GAMMA_OFF + NROWS * DIM_S * DIM_M)
#define STEP_OFF  (BETA_OFF  + NROWS * DIM_S * DIM_M)
#define ERRO_OFF  (STEP_OFF  + NROWS * DIM_D)
#define AUX_OFF   (ERRO_OFF  + NROWS * DIM_D)
#define CMASK_OFF (AUX_OFF   + NROWS * 8)
#define RAW_OFF   (CMASK_OFF + NROWS * DIM_S)

// ---------------------------------------------------------------------------
// Scratch (static device globals: allocation-free)
// ---------------------------------------------------------------------------
__device__ float g_qstep[NROWS * DIM_D];
__device__ float g_qerr [NROWS * DIM_D];
__device__ float g_stepproto [DIM_S * DIM_D];
__device__ float g_stepprotoT[DIM_D * DIM_S];
__device__ float g_errproto[ERR_ROWS * DIM_D];
__device__ float g_rinv_qstep[NROWS];
__device__ float g_rinv_qerr [NROWS];

// ---------------------------------------------------------------------------
// TF32 helpers
// ---------------------------------------------------------------------------
__device__ __forceinline__ void split_tf32(float x, uint32_t& hi, uint32_t& lo) {
    uint32_t h = __float_as_uint(x) & 0xFFFFE000u;
    hi = h;
    lo = __float_as_uint(x - __uint_as_float(h));
}

__device__ __forceinline__ void mma_m16n8k8(float* c, const uint32_t* a, const uint32_t* b) {
    asm volatile(
        "mma.sync.aligned.m16n8k8.row.col.f32.tf32.tf32.f32 "
        "{%0,%1,%2,%3}, {%4,%5,%6,%7}, {%8,%9}, {%0,%1,%2,%3};\n"
        : "+f"(c[0]), "+f"(c[1]), "+f"(c[2]), "+f"(c[3])
        : "r"(a[0]), "r"(a[1]), "r"(a[2]), "r"(a[3]), "r"(b[0]), "r"(b[1]));
}

// ---------------------------------------------------------------------------
// GEMM inner body shared by both kernels (BM=128, BN=128, WM=32, WN=64,
// 256 threads, N=K=512), R9 champion schedule.
// ---------------------------------------------------------------------------
struct Proj4Args {
    const float* A[4];
    const float* B[4];
    const float* bias[4];
    float*       C[4];
};

__global__ void __launch_bounds__(256)
mma_proj4(Proj4Args args)
{
    constexpr int BM = 128, BN = 128, WM = 32, WN = 64;
    constexpr int WARPS_M = BM / WM;           // 4
    constexpr int NTHREADS = 256;
    constexpr int FM = WM / 16;                // 2
    constexpr int FN = WN / 8;                 // 8
    constexpr int LDA = 20;
    constexpr int LA = BM * 4 / NTHREADS;      // 2
    constexpr int LB = BN * 4 / NTHREADS;      // 2
    constexpr int N = 512, K = 512;

    // segment decode: [0,256) qstep, [256,512) qerr, [512,576) eproto, [576,580) sproto
    int cid = blockIdx.x;
    int seg, li;
    if (cid < 256)      { seg = 0; li = cid; }
    else if (cid < 512) { seg = 1; li = cid - 256; }
    else if (cid < 576) { seg = 2; li = cid - 512; }
    else                { seg = 3; li = cid - 576; }
    const float* A = args.A[seg];
    const float* B = args.B[seg];
    const float* bias = args.bias[seg];
    float* C = args.C[seg];
    const int bm = (li >> 2) * BM;
    const int bn = (li & 3) * BN;

    __shared__ __align__(16) float sA[2][BM * LDA];
    __shared__ __align__(16) float sB[2][BN * LDA];

    const int tid = threadIdx.x;
    const int lane = tid & 31;
    const int warp = tid >> 5;
    const int gid = lane >> 2, tig = lane & 3;
    const int wm0 = (warp % WARPS_M) * WM;
    const int wn0 = (warp / WARPS_M) * WN;

    float acc[FM][FN][4];
#pragma unroll
    for (int i = 0; i < FM; i++)
#pragma unroll
        for (int j = 0; j < FN; j++)
#pragma unroll
            for (int q = 0; q < 4; q++) acc[i][j][q] = 0.f;

    float4 stageA[LA], stageB[LB];

    auto gload = [&](int kt) {
        int k0 = kt * 16;
#pragma unroll
        for (int i = 0; i < LA; i++) {
            int c = tid + i * NTHREADS;
            int row = c >> 2, kc = (c & 3) << 2;
            stageA[i] = *(const float4*)(A + (size_t)(bm + row) * K + k0 + kc);
        }
#pragma unroll
        for (int i = 0; i < LB; i++) {
            int c = tid + i * NTHREADS;
            int row = c >> 2, kc = (c & 3) << 2;
            stageB[i] = *(const float4*)(B + (size_t)(bn + row) * K + k0 + kc);
        }
    };

    auto sstore = [&](int buf) {
#pragma unroll
        for (int i = 0; i < LA; i++) {
            int c = tid + i * NTHREADS;
            int row = c >> 2, kc = (c & 3) << 2;
            *(float4*)(&sA[buf][row * LDA + kc]) = stageA[i];
        }
#pragma unroll
        for (int i = 0; i < LB; i++) {
            int c = tid + i * NTHREADS;
            int row = c >> 2, kc = (c & 3) << 2;
            *(float4*)(&sB[buf][row * LDA + kc]) = stageB[i];
        }
    };

    const int KT = K >> 4;
    gload(0);
    sstore(0);
    __syncthreads();

    int buf = 0;
    for (int kt = 0; kt < KT; kt++) {
        if (kt + 1 < KT) gload(kt + 1);

#pragma unroll
        for (int ks = 0; ks < 2; ks++) {
            uint32_t ahi[FM][4], alo[FM][4];
#pragma unroll
            for (int fm = 0; fm < FM; fm++) {
                int r = wm0 + fm * 16 + gid;
                float x0 = sA[buf][r * LDA + ks * 8 + tig];
                float x1 = sA[buf][(r + 8) * LDA + ks * 8 + tig];
                float x2 = sA[buf][r * LDA + ks * 8 + tig + 4];
                float x3 = sA[buf][(r + 8) * LDA + ks * 8 + tig + 4];
                split_tf32(x0, ahi[fm][0], alo[fm][0]);
                split_tf32(x1, ahi[fm][1], alo[fm][1]);
                split_tf32(x2, ahi[fm][2], alo[fm][2]);
                split_tf32(x3, ahi[fm][3], alo[fm][3]);
            }
#pragma unroll
            for (int fn = 0; fn < FN; fn++) {
                int n = wn0 + fn * 8 + gid;
                float y0 = sB[buf][n * LDA + ks * 8 + tig];
                float y1 = sB[buf][n * LDA + ks * 8 + tig + 4];
                uint32_t bhi[2], blo[2];
                split_tf32(y0, bhi[0], blo[0]);
                split_tf32(y1, bhi[1], blo[1]);
#pragma unroll
                for (int fm = 0; fm < FM; fm++) {
                    mma_m16n8k8(acc[fm][fn], alo[fm], bhi);
                    mma_m16n8k8(acc[fm][fn], ahi[fm], blo);
                    mma_m16n8k8(acc[fm][fn], ahi[fm], bhi);
                }
            }
        }

        if (kt + 1 < KT) sstore(buf ^ 1);
        __syncthreads();
        buf ^= 1;
    }

#pragma unroll
    for (int fm = 0; fm < FM; fm++) {
#pragma unroll
        for (int fn = 0; fn < FN; fn++) {
            int r0 = bm + wm0 + fm * 16 + gid;
            int c0 = bn + wn0 + fn * 8 + 2 * tig;
            float bx = bias[c0], by = bias[c0 + 1];
            float2 v0, v1;
            v0.x = acc[fm][fn][0] + bx;
            v0.y = acc[fm][fn][1] + by;
            v1.x = acc[fm][fn][2] + bx;
            v1.y = acc[fm][fn][3] + by;
            *(float2*)(C + (size_t)r0 * N + c0) = v0;
            *(float2*)(C + (size_t)(r0 + 8) * N + c0) = v1;
        }
    }
}

// ---------------------------------------------------------------------------
// General GEMM (R9 champion) with optional per-row output scale.
// ---------------------------------------------------------------------------
template<int BM, int BN, int WM, int WN>
__global__ void __launch_bounds__((BM / WM) * (BN / WN) * 32)
mma_nt(const float* __restrict__ A, const float* __restrict__ B,
       const float* __restrict__ bias, const float* __restrict__ rowscale,
       float* __restrict__ C, int M, int N, int K, float scale)
{
    constexpr int WARPS_M = BM / WM;
    constexpr int WARPS_N = BN / WN;
    constexpr int NTHREADS = WARPS_M * WARPS_N * 32;
    constexpr int FM = WM / 16;
    constexpr int FN = WN / 8;
    constexpr int LDA = 20;
    constexpr int LA = BM * 4 / NTHREADS;
    constexpr int LB = BN * 4 / NTHREADS;

    __shared__ __align__(16) float sA[2][BM * LDA];
    __shared__ __align__(16) float sB[2][BN * LDA];

    const int tid = threadIdx.x;
    const int lane = tid & 31;
    const int warp = tid >> 5;
    const int gid = lane >> 2, tig = lane & 3;
    const int wm0 = (warp % WARPS_M) * WM;
    const int wn0 = (warp / WARPS_M) * WN;
    const int bm = blockIdx.y * BM;
    const int bn = blockIdx.x * BN;

    float acc[FM][FN][4];
#pragma unroll
    for (int i = 0; i < FM; i++)
#pragma unroll
        for (int j = 0; j < FN; j++)
#pragma unroll
            for (int q = 0; q < 4; q++) acc[i][j][q] = 0.f;

    float4 stageA[LA], stageB[LB];

    auto gload = [&](int kt) {
        int k0 = kt * 16;
#pragma unroll
        for (int i = 0; i < LA; i++) {
            int c = tid + i * NTHREADS;
            int row = c >> 2, kc = (c & 3) << 2;
            stageA[i] = *(const float4*)(A + (size_t)(bm + row) * K + k0 + kc);
        }
#pragma unroll
        for (int i = 0; i < LB; i++) {
            int c = tid + i * NTHREADS;
            int row = c >> 2, kc = (c & 3) << 2;
            stageB[i] = *(const float4*)(B + (size_t)(bn + row) * K + k0 + kc);
        }
    };

    auto sstore = [&](int buf) {
#pragma unroll
        for (int i = 0; i < LA; i++) {
            int c = tid + i * NTHREADS;
            int row = c >> 2, kc = (c & 3) << 2;
            *(float4*)(&sA[buf][row * LDA + kc]) = stageA[i];
        }
#pragma unroll
        for (int i = 0; i < LB; i++) {
            int c = tid + i * NTHREADS;
            int row = c >> 2, kc = (c & 3) << 2;
            *(float4*)(&sB[buf][row * LDA + kc]) = stageB[i];
        }
    };

    const int KT = K >> 4;
    gload(0);
    sstore(0);
    __syncthreads();

    int buf = 0;
    for (int kt = 0; kt < KT; kt++) {
        if (kt + 1 < KT) gload(kt + 1);

#pragma unroll
        for (int ks = 0; ks < 2; ks++) {
            uint32_t ahi[FM][4], alo[FM][4];
#pragma unroll
            for (int fm = 0; fm < FM; fm++) {
                int r = wm0 + fm * 16 + gid;
                float x0 = sA[buf][r * LDA + ks * 8 + tig];
                float x1 = sA[buf][(r + 8) * LDA + ks * 8 + tig];
                float x2 = sA[buf][r * LDA + ks * 8 + tig + 4];
                float x3 = sA[buf][(r + 8) * LDA + ks * 8 + tig + 4];
                split_tf32(x0, ahi[fm][0], alo[fm][0]);
                split_tf32(x1, ahi[fm][1], alo[fm][1]);
                split_tf32(x2, ahi[fm][2], alo[fm][2]);
                split_tf32(x3, ahi[fm][3], alo[fm][3]);
            }
#pragma unroll
            for (int fn = 0; fn < FN; fn++) {
                int n = wn0 + fn * 8 + gid;
                float y0 = sB[buf][n * LDA + ks * 8 + tig];
                float y1 = sB[buf][n * LDA + ks * 8 + tig + 4];
                uint32_t bhi[2], blo[2];
                split_tf32(y0, bhi[0], blo[0]);
                split_tf32(y1, bhi[1], blo[1]);
#pragma unroll
                for (int fm = 0; fm < FM; fm++) {
                    mma_m16n8k8(acc[fm][fn], alo[fm], bhi);
                    mma_m16n8k8(acc[fm][fn], ahi[fm], blo);
                    mma_m16n8k8(acc[fm][fn], ahi[fm], bhi);
                }
            }
        }

        if (kt + 1 < KT) sstore(buf ^ 1);
        __syncthreads();
        buf ^= 1;
    }

#pragma unroll
    for (int fm = 0; fm < FM; fm++) {
        int r0 = bm + wm0 + fm * 16 + gid;
        float rs0 = scale, rs1 = scale;
        if (rowscale) { rs0 *= rowscale[r0]; rs1 *= rowscale[r0 + 8]; }
#pragma unroll
        for (int fn = 0; fn < FN; fn++) {
            int c0 = bn + wn0 + fn * 8 + 2 * tig;
            float bx = 0.f, by = 0.f;
            if (bias) { bx = bias[c0]; by = bias[c0 + 1]; }
            float2 v0, v1;
            v0.x = (acc[fm][fn][0] + bx) * rs0;
            v0.y = (acc[fm][fn][1] + by) * rs0;
            v1.x = (acc[fm][fn][2] + bx) * rs1;
            v1.y = (acc[fm][fn][3] + by) * rs1;
            *(float2*)(C + (size_t)r0 * N + c0) = v0;
            *(float2*)(C + (size_t)(r0 + 8) * N + c0) = v1;
        }
    }
}

// ---------------------------------------------------------------------------
// Fused cleanup: one warp-task per row.
//   [0, 8192)        rinv of qstep row
//   [8192, 16384)    rinv of qerr row
//   [16384, 18432)   in-place normalize of eproto row
//   [18432, 18560)   in-place normalize of sproto row + scatter into sprotoT
// ---------------------------------------------------------------------------
__global__ void __launch_bounds__(128) cleanup_kernel(
    const float* __restrict__ qstep, const float* __restrict__ qerr,
    float* __restrict__ eproto, float* __restrict__ sproto,
    float* __restrict__ sprotoT, float* __restrict__ rq, float* __restrict__ re)
{
    int wi = blockIdx.x * 4 + (threadIdx.x >> 5);
    int lane = threadIdx.x & 31;

    if (wi < 2 * NROWS) {               // rinv tasks (read-only)
        const float* X = (wi < NROWS) ? qstep : qerr;
        int row = (wi < NROWS) ? wi : wi - NROWS;
        const float4* p = (const float4*)(X + (size_t)row * DIM_D);
        float ss = 0.f;
#pragma unroll
        for (int i = 0; i < 4; i++) {
            float4 v = p[lane + 32 * i];
            ss += v.x * v.x + v.y * v.y + v.z * v.z + v.w * v.w;
        }
#pragma unroll
        for (int o = 16; o > 0; o >>= 1) ss += __shfl_xor_sync(0xffffffffu, ss, o);
        if (lane == 0) {
            float inv = 1.f / fmaxf(sqrtf(ss), 1e-8f);
            if (wi < NROWS) rq[row] = inv; else re[row] = inv;
        }
    } else if (wi < 2 * NROWS + ERR_ROWS) {   // eproto normalize
        int row = wi - 2 * NROWS;
        float4* p = (float4*)(eproto + (size_t)row * DIM_D);
        float4 v[4];
        float ss = 0.f;
#pragma unroll
        for (int i = 0; i < 4; i++) {
            v[i] = p[lane + 32 * i];
            ss += v[i].x * v[i].x + v[i].y * v[i].y + v[i].z * v[i].z + v[i].w * v[i].w;
        }
#pragma unroll
        for (int o = 16; o > 0; o >>= 1) ss += __shfl_xor_sync(0xffffffffu, ss, o);
        float inv = 1.f / fmaxf(sqrtf(ss), 1e-8f);
#pragma unroll
        for (int i = 0; i < 4; i++) {
            v[i].x *= inv; v[i].y *= inv; v[i].z *= inv; v[i].w *= inv;
            p[lane + 32 * i] = v[i];
        }
    } else if (wi < 2 * NROWS + ERR_ROWS + DIM_S) {  // sproto normalize + transpose
        int row = wi - (2 * NROWS + ERR_ROWS);
        float4* p = (float4*)(sproto + (size_t)row * DIM_D);
        float4 v[4];
        float ss = 0.f;
#pragma unroll
        for (int i = 0; i < 4; i++) {
            v[i] = p[lane + 32 * i];
            ss += v[i].x * v[i].x + v[i].y * v[i].y + v[i].z * v[i].z + v[i].w * v[i].w;
        }
#pragma unroll
        for (int o = 16; o > 0; o >>= 1) ss += __shfl_xor_sync(0xffffffffu, ss, o);
        float inv = 1.f / fmaxf(sqrtf(ss), 1e-8f);
#pragma unroll
        for (int i = 0; i < 4; i++) {
            v[i].x *= inv; v[i].y *= inv; v[i].z *= inv; v[i].w *= inv;
            p[lane + 32 * i] = v[i];
            int d = 4 * (lane + 32 * i);
            sprotoT[(size_t)(d + 0) * DIM_S + row] = v[i].x;
            sprotoT[(size_t)(d + 1) * DIM_S + row] = v[i].y;
            sprotoT[(size_t)(d + 2) * DIM_S + row] = v[i].z;
            sprotoT[(size_t)(d + 3) * DIM_S + row] = v[i].w;
        }
    }
}

// ---------------------------------------------------------------------------
// Warp-synchronous DAG scan — R9 VERSION VERBATIM (measured good).
// ---------------------------------------------------------------------------
__global__ __launch_bounds__(32) void scan_kernel(
    const float* __restrict__ raw,
    float* __restrict__ alpha_out,
    float* __restrict__ aux)
{
    const unsigned FULL = 0xffffffffu;
    int b = blockIdx.x;
    int l = threadIdx.x;

    int s0 = 4 * l;
    bool h1[4], h2[4], h4[4], h8[4];
    float invc[4];
#pragma unroll
    for (int i = 0; i < 4; i++) {
        int s = s0 + i;
        h1[i] = s >= 1; h2[i] = s >= 2; h4[i] = s >= 4; h8[i] = s >= 8;
        int c = (int)h1[i] + (int)h2[i] + (int)h4[i] + (int)h8[i];
        invc[i] = c ? 1.f / (float)c : 0.f;
    }

    float p[4] = {1.f / DIM_S, 1.f / DIM_S, 1.f / DIM_S, 1.f / DIM_S};

    const float* rp = raw + (size_t)b * DIM_T * DIM_S;
    float* ap = alpha_out + (size_t)b * DIM_T * DIM_S;
    float4 rv = *(const float4*)(rp + s0);

    for (int t = 0; t < DIM_T; t++) {
        float4 cur = rv;
        if (t + 1 < DIM_T) rv = *(const float4*)(rp + (size_t)(t + 1) * DIM_S + s0);
        float craw[4] = {cur.x, cur.y, cur.z, cur.w};

        float u1[4], u2[4];
#pragma unroll
        for (int i = 0; i < 4; i++) {
            u1[i] = __shfl_up_sync(FULL, p[i], 1);
            u2[i] = __shfl_up_sync(FULL, p[i], 2);
        }
        float v1[4] = {u1[3], p[0], p[1], p[2]};
        float v2[4] = {u1[2], u1[3], p[0], p[1]};

        float e[4];
        float les = 0.f, lms = 0.f, lmm = -1e30f;
#pragma unroll
        for (int i = 0; i < 4; i++) {
            float pm = 0.f, px = -1e30f;
            if (h1[i]) { pm += v1[i]; px = fmaxf(px, v1[i]); }
            if (h2[i]) { pm += v2[i]; px = fmaxf(px, v2[i]); }
            if (h4[i]) { pm += u1[i]; px = fmaxf(px, u1[i]); }
            if (h8[i]) { pm += u2[i]; px = fmaxf(px, u2[i]); }
            float pmean = pm * invc[i];
            float pmax  = h1[i] ? px : 0.f;
            float mass = fmaxf(LAM_SELF * p[i] + LAM_SUCC * pmax + LAM_PRED * pmean, 1e-8f);
            float logit = craw[i] + LAM_TOPO * __logf(mass);
            e[i] = __expf(logit);
            les += e[i];
            lms += mass;
            lmm = fmaxf(lmm, mass);
        }

#pragma unroll
        for (int o = 16; o > 0; o >>= 1) {
            les += __shfl_xor_sync(FULL, les, o);
            lms += __shfl_xor_sync(FULL, lms, o);
            lmm = fmaxf(lmm, __shfl_xor_sync(FULL, lmm, o));
        }

        float invZ = __fdividef(1.f, les);
        float4 av;
        av.x = e[0] * invZ; av.y = e[1] * invZ;
        av.z = e[2] * invZ; av.w = e[3] * invZ;
        *(float4*)(ap + (size_t)t * DIM_S + s0) = av;
        p[0] = av.x; p[1] = av.y; p[2] = av.z; p[3] = av.w;

        if (l == 0) {
            float* ax = aux + ((size_t)b * DIM_T + t) * 8;
            ax[5] = lms * (1.0f / DIM_S);
            ax[6] = lmm;
        }
    }
}

// ---------------------------------------------------------------------------
// Per-(b,t) row kernel (R13/R16 champion, fused qerr normalization).
// ---------------------------------------------------------------------------
__global__ __launch_bounds__(128) void sparse_kernel(
    const float* __restrict__ alpha,
    const float* __restrict__ qerr,
    const float* __restrict__ rinv,
    const float* __restrict__ errproto,
    float* __restrict__ out)
{
    int row = blockIdx.x;
    int tid = threadIdx.x;
    int lane = tid & 31, w = tid >> 5;

    __shared__ __align__(16) float sh_q[DIM_D];
    __shared__ float warp_vals[4][K_MAX];
    __shared__ int   warp_idx [4][K_MAX];
    __shared__ int   sel_idx[K_MAX];
    __shared__ float sel_alpha[K_MAX];
    __shared__ int   sel_flag[DIM_S];
    __shared__ int   sh_count;
    __shared__ float sh_top1, sh_top2;
    __shared__ float sh_logits[K_MAX][DIM_M];
    __shared__ float sh_beta [K_MAX][DIM_M];
    __shared__ float sh_gamma[K_MAX][DIM_M];
    __shared__ float sh_H[K_MAX];
    __shared__ float sh_gsum_j[K_MAX];
    __shared__ float redA[4], redB[4];

    float a = alpha[(size_t)row * DIM_S + tid];
    sel_flag[tid] = 0;
    {
        float rq = rinv[row];
        float4 qv = ((const float4*)(qerr + (size_t)row * DIM_D))[tid];
        qv.x *= rq; qv.y *= rq; qv.z *= rq; qv.w *= rq;
        ((float4*)sh_q)[tid] = qv;
    }
    __syncthreads();

    {
        float v = a;
        int id = tid;
#pragma unroll
        for (int j = 0; j < K_MAX; j++) {
            float bv = v; int bi = id;
#pragma unroll
            for (int o = 16; o > 0; o >>= 1) {
                float ov = __shfl_xor_sync(0xffffffffu, bv, o);
                int   oi = __shfl_xor_sync(0xffffffffu, bi, o);
                if (ov > bv || (ov == bv && oi < bi)) { bv = ov; bi = oi; }
            }
            if (lane == 0) { warp_vals[w][j] = bv; warp_idx[w][j] = bi; }
            if (id == bi) v = -1e30f;
        }
    }
    __syncthreads();

    if (tid == 0) {
        float vals[20]; int ids[20]; bool used[20];
#pragma unroll
        for (int w2 = 0; w2 < 4; w2++)
#pragma unroll
            for (int j = 0; j < K_MAX; j++) {
                vals[w2 * K_MAX + j] = warp_vals[w2][j];
                ids [w2 * K_MAX + j] = warp_idx [w2][j];
                used[w2 * K_MAX + j] = false;
            }
        float prefix = 0.f, top1 = 0.f, top2 = 0.f;
        int cnt = 0;
        for (int j = 0; j < K_MAX; j++) {
            int best = -1;
            for (int c = 0; c < 20; c++) {
                if (used[c]) continue;
                if (best < 0 || vals[c] > vals[best] ||
                    (vals[c] == vals[best] && ids[c] < ids[best])) best = c;
            }
            used[best] = true;
            if (j == 0) top1 = vals[best];
            if (j == 1) top2 = vals[best];
            bool keep = prefix < RHO_ERR;
            prefix += vals[best];
            if (keep) {
                sel_idx[cnt] = ids[best];
                sel_alpha[cnt] = vals[best];
                sel_flag[ids[best]] = cnt + 1;
                cnt++;
            }
        }
        sh_count = cnt;
        sh_top1 = top1;
        sh_top2 = top2;
    }
    __syncthreads();
    int count = sh_count;

    int f = sel_flag[tid];
    out[CMASK_OFF + (size_t)row * DIM_S + tid] = f ? 1.f : 0.f;

    for (int j = 0; j < count; j++) {
        int s = sel_idx[j];
        const float* ep = errproto + (size_t)(s * DIM_M + w * 4) * DIM_D;
#pragma unroll
        for (int mi = 0; mi < 4; mi++) {
            const float4* er = (const float4*)(ep + (size_t)mi * DIM_D);
            float sum = 0.f;
#pragma unroll
            for (int i = 0; i < 4; i++) {
                float4 q = ((const float4*)sh_q)[i * 32 + lane];
                float4 e = er[i * 32 + lane];
                sum += q.x * e.x + q.y * e.y + q.z * e.z + q.w * e.w;
            }
#pragma unroll
            for (int o = 16; o > 0; o >>= 1) sum += __shfl_xor_sync(0xffffffffu, sum, o);
            if (lane == 0) sh_logits[j][w * 4 + mi] = sum * (1.0f / TAU_ERR);
        }
    }
    __syncthreads();

    if (tid < count) {
        float l[DIM_M];
        float mx = -1e30f;
#pragma unroll
        for (int m = 0; m < DIM_M; m++) { l[m] = sh_logits[tid][m]; mx = fmaxf(mx, l[m]); }
        float sum = 0.f;
#pragma unroll
        for (int m = 0; m < DIM_M; m++) { l[m] = __expf(l[m] - mx); sum += l[m]; }
        float inv = 1.f / sum;
        float as_ = sel_alpha[tid];
        float H = 0.f, gs = 0.f;
#pragma unroll
        for (int m = 0; m < DIM_M; m++) {
            float be = l[m] * inv;
            sh_beta[tid][m] = be;
            float g = as_ * be;
            sh_gamma[tid][m] = g;
            gs += g;
            H -= be * __logf(fmaxf(be, 1e-8f));
        }
        sh_H[tid] = H;
        sh_gsum_j[tid] = gs;
    }
    __syncthreads();

    {
        float4* brow = (float4*)(out + BETA_OFF  + (size_t)row * (DIM_S * DIM_M));
        float4* grow = (float4*)(out + GAMMA_OFF + (size_t)row * (DIM_S * DIM_M));
#pragma unroll
        for (int q = 0; q < 4; q++) {
            int fi = q * 128 + tid;
            int s  = fi >> 2;
            int m0 = (fi & 3) << 2;
            int fj = sel_flag[s];
            float4 bv, gv;
            if (fj) {
                int j = fj - 1;
                bv = make_float4(sh_beta[j][m0], sh_beta[j][m0+1],
                                 sh_beta[j][m0+2], sh_beta[j][m0+3]);
                gv = make_float4(sh_gamma[j][m0], sh_gamma[j][m0+1],
                                 sh_gamma[j][m0+2], sh_gamma[j][m0+3]);
            } else {
                bv = make_float4(0.0625f, 0.0625f, 0.0625f, 0.0625f);
                gv = make_float4(0.f, 0.f, 0.f, 0.f);
            }
            brow[fi] = bv;
            grow[fi] = gv;
        }
    }

    {
        float4 acc = make_float4(0.f, 0.f, 0.f, 0.f);
        for (int j = 0; j < count; j++) {
            int s = sel_idx[j];
            const float* base = errproto + (size_t)s * DIM_M * DIM_D + tid * 4;
#pragma unroll
            for (int m = 0; m < DIM_M; m++) {
                float g = sh_gamma[j][m];
                float4 e = *(const float4*)(base + (size_t)m * DIM_D);
                acc.x += g * e.x; acc.y += g * e.y; acc.z += g * e.z; acc.w += g * e.w;
            }
        }
        *(float4*)(out + ERRO_OFF + (size_t)row * DIM_D + tid * 4) = acc;
    }

    {
        float ent = -a * __logf(fmaxf(a, 1e-8f));
        float ht = (f ? sh_H[f - 1] : LOG16) * a;
#pragma unroll
        for (int o = 16; o > 0; o >>= 1) {
            ent += __shfl_xor_sync(0xffffffffu, ent, o);
            ht  += __shfl_xor_sync(0xffffffffu, ht, o);
        }
        if (lane == 0) { redA[w] = ent; redB[w] = ht; }
        __syncthreads();
        if (tid == 0) {
            float entropy = redA[0] + redA[1] + redA[2] + redA[3];
            float hsum    = redB[0] + redB[1] + redB[2] + redB[3];
            float gsum = 0.f;
            for (int j = 0; j < count; j++) gsum += sh_gsum_j[j];
            float* ax = out + AUX_OFF + (size_t)row * 8;
            ax[0] = entropy;
            ax[1] = sh_top1;
            ax[2] = sh_top1 - sh_top2;
            ax[3] = gsum;
            ax[4] = hsum;
            ax[7] = (float)count / (float)K_MAX;
        }
    }
}

// ---------------------------------------------------------------------------
// Launch
// ---------------------------------------------------------------------------
extern "C" void kernel_launch(void* const* d_in, const int* in_sizes, int n_in,
                              void* d_out, int out_size)
{
    (void)in_sizes; (void)n_in; (void)out_size;
    const float* frame   = (const float*)d_in[0];
    const float* stepp   = (const float*)d_in[1];
    const float* errp    = (const float*)d_in[2];
    const float* Wq_step = (const float*)d_in[3];
    const float* bq_step = (const float*)d_in[4];
    const float* Wq_err  = (const float*)d_in[5];
    const float* bq_err  = (const float*)d_in[6];
    const float* Wa_step = (const float*)d_in[7];
    const float* ba_step = (const float*)d_in[8];
    const float* Wa_err  = (const float*)d_in[9];
    const float* ba_err  = (const float*)d_in[10];
    float* out = (float*)d_out;

    float *qstep, *qerr, *sproto, *sprotoT, *eproto, *rq, *re;
    cudaGetSymbolAddress((void**)&qstep,   g_qstep);
    cudaGetSymbolAddress((void**)&qerr,    g_qerr);
    cudaGetSymbolAddress((void**)&sproto,  g_stepproto);
    cudaGetSymbolAddress((void**)&sprotoT, g_stepprotoT);
    cudaGetSymbolAddress((void**)&eproto,  g_errproto);
    cudaGetSymbolAddress((void**)&rq,      g_rinv_qstep);
    cudaGetSymbolAddress((void**)&re,      g_rinv_qerr);

    // 0: ALL FOUR projections in one launch (580 CTAs, ~4 full waves)
    Proj4Args pa;
    pa.A[0] = frame;   pa.B[0] = Wq_step; pa.bias[0] = bq_step; pa.C[0] = qstep;
    pa.A[1] = frame;   pa.B[1] = Wq_err;  pa.bias[1] = bq_err;  pa.C[1] = qerr;
    pa.A[2] = errp;    pa.B[2] = Wa_err;  pa.bias[2] = ba_err;  pa.C[2] = eproto;
    pa.A[3] = stepp;   pa.B[3] = Wa_step; pa.bias[3] = ba_step; pa.C[3] = sproto;
    mma_proj4<<<580, 256>>>(pa);

    // 1: fused cleanup (rinv qstep/qerr, normalize eproto, normalize+transpose sproto)
    cleanup_kernel<<<(2 * NROWS + ERR_ROWS + DIM_S) / 4, 128>>>(
        qstep, qerr, eproto, sproto, sprotoT, rq, re);

    // 2: raw_step_logits = rowscale * (qstep @ sproto^T) / tau
    mma_nt<64, 128, 32, 64><<<dim3(DIM_S / 128, NROWS / 64), 128>>>(
        qstep, sproto, nullptr, rq, out + RAW_OFF, NROWS, DIM_S, DIM_D, 1.f / TAU_STEP);

    // 3: warp-synchronous DAG scan (profiled slot — first direct scan profile)
    scan_kernel<<<DIM_B, 32>>>(out + RAW_OFF, out + ALPHA_OFF, out + AUX_OFF);

    // 4: sparse error path
    sparse_kernel<<<NROWS, 128>>>(out + ALPHA_OFF, qerr, re, eproto, out);

    // 5: step_sem_obs = alpha @ step_proto
    mma_nt<128, 128, 32, 64><<<dim3(DIM_D / 128, NROWS / 128), 256>>>(
        out + ALPHA_OFF, sprotoT, nullptr, nullptr, out + STEP_OFF, NROWS, DIM_D, DIM_S, 1.f);
}